// round 17
// baseline (speedup 1.0000x reference)
#include <cuda_runtime.h>
#include <math.h>

#define BDIM 128
#define NPTS 64
#define PI_F      3.14159265358979f
#define INV_PI_F  0.318309886183791f
#define MAGIC_F   12582912.0f
#define EPS_U     3.1830989e-5f   // 1e-4 / pi

__device__ __forceinline__ float rcp_approx(float x) {
    float r; asm("rcp.approx.f32 %0, %1;" : "=f"(r) : "f"(x)); return r;
}

// 16 blocks/SM x 128 thr x 32 regs = 64K: cap regs at 32 so the whole
// 2048-block grid is resident in one wave; full unroll for scheduler freedom.
__global__ __launch_bounds__(BDIM, 16)
void scatter_polygon_kernel(const float* __restrict__ points,
                            const float* __restrict__ phi,
                            float* __restrict__ out,
                            int B, int N) {
    __shared__ float4 spts[NPTS / 2];   // two points per float4

    const int b = blockIdx.y;
    const int n = blockIdx.x * BDIM + threadIdx.x;

    reinterpret_cast<float*>(spts)[threadIdx.x] = points[b * 2 * NPTS + threadIdx.x];
    __syncthreads();

    // Per-angle constants — accurate libm sincos (phi ~ pi/2 -> |q| tiny,
    // scale ~ 1/delta^2 huge; q needs ~1e-7 absolute accuracy).
    float sphi, cphi;
    sincosf(phi[n], &sphi, &cphi);
    const float qx = cphi;
    const float qy = sphi - 1.0f;
    const float scale = 1.0f / fabsf(qx * qx + qy * qy);
    const float qxp = qx * INV_PI_F;
    const float qyp = qy * INV_PI_F;
    const float nqyp = -qyp;

    // Scalar eval: u = (p.q)/pi, hc = (p.q_cross)/pi, (s,c) = sincos(p.q)
    // via mod-pi reduction; Chebyshev-economized sin(pi f) deg-7 /
    // cos(pi f) deg-8 on [-1/2,1/2]. Smooth error <= ~4e-6; leading terms
    // exact -> relative accuracy preserved for small arguments.
    auto eval1 = [&](float px, float py,
                     float& u, float& hc, float& s, float& c) {
        u  = fmaf(px, qxp, py * qyp);
        hc = fmaf(py, qxp, px * nqyp);
        const float t  = u + MAGIC_F;
        const float nf = t - MAGIC_F;         // round(u)
        const float f  = u - nf;              // exact (Sterbenz)
        const float f2 = f * f;

        float w = fmaf(f2, -0.55305645f, 2.54150018f);
        w = fmaf(f2, w, -5.16711112f);
        w = fmaf(f2, w, 3.14158137f);
        const float sp = f * w;               // sin(pi f), econ deg 7

        float v = fmaf(f2, 0.21920132f, -1.33173449f);
        v = fmaf(f2, v, 4.05839710f);
        v = fmaf(f2, v, -4.93479236f);
        const float cp = fmaf(f2, v, 1.0f);   // cos(pi f), econ deg 8

        const int g = __float_as_int(t) << 31;   // (-1)^n sign bit
        s = __int_as_float(__float_as_int(sp) ^ g);
        c = __int_as_float(__float_as_int(cp) ^ g);
    };

    float sum_r = 0.0f, nsum_i = 0.0f;        // nsum_i accumulates -imag

    // prev = point[NPTS-1]
    float up, hp, sprev, cprev;
    {
        const float4 pl = spts[NPTS / 2 - 1];
        eval1(pl.z, pl.w, up, hp, sprev, cprev);
    }

    // edge (prev -> cur). One select chooses the multiplier:
    //  case1 (|ddq|>=eps): f = dc*rcp(du);  r += f*(cprev-cc), -i += f*(sc-sprev)
    //  case2:              f = dc*pi;       r += f*sprev,      -i += f*cprev
    auto edge = [&](float uc, float hc, float sc, float cc) {
        const float du = uc - up;             // ddq / pi
        const float dc = hc - hp;             // ddqc / pi
        const float rin = rcp_approx(du);
        const bool big = fabsf(du) >= EPS_U;
        const float m  = big ? rin : PI_F;
        const float f  = dc * m;
        const float vr = big ? (cprev - cc) : sprev;
        const float vi = big ? (sc - sprev) : cprev;
        sum_r  = fmaf(f, vr, sum_r);
        nsum_i = fmaf(f, vi, nsum_i);
        up = uc; hp = hc; sprev = sc; cprev = cc;
    };

#pragma unroll
    for (int kk = 0; kk < NPTS / 2; ++kk) {   // fully unrolled, 16 iterations
        const float4 pc = spts[kk];           // points 2kk (x,y), 2kk+1 (z,w)
        float u0, h0, s0, c0, u1, h1, s1, c1;
        eval1(pc.x, pc.y, u0, h0, s0, c0);    // two independent scalar chains
        eval1(pc.z, pc.w, u1, h1, s1, c1);
        edge(u0, h0, s0, c0);
        edge(u1, h1, s1, c1);
    }

    out[(b * 2 + 0) * N + n] = scale * sum_r;
    out[(b * 2 + 1) * N + n] = -(scale * nsum_i);
}

extern "C" void kernel_launch(void* const* d_in, const int* in_sizes, int n_in,
                              void* d_out, int out_size) {
    const float* points = (const float*)d_in[0];  // [B, 64, 2] f32
    const float* phi    = (const float*)d_in[1];  // [N] f32
    float* out = (float*)d_out;                   // [B, 2, N] f32

    const int N = in_sizes[1];
    const int B = in_sizes[0] / (2 * NPTS);

    dim3 grid((N + BDIM - 1) / BDIM, B);
    scatter_polygon_kernel<<<grid, BDIM>>>(points, phi, out, B, N);
}